// round 11
// baseline (speedup 1.0000x reference)
#include <cuda_runtime.h>
#include <cstdint>

// LocalAggregationLoss — warp-level work stealing to kill multi-CTA spread.
//   Units: (b, eighth) = 25 row-pairs; 8192 units grabbed via atomic ticket.
//   K0: zero ticket + accumulators
//   K1: persistent-ish main kernel, warps steal units, atomicAdd partials
//   K2: out[b] = log(acc_bg) - log(acc_cl)

#define DIM    128
#define KNEI   200
#define NB     1024
#define TINV   (1.0f / 0.07f)
#define PPU    25                 // pairs per unit
#define UNITS  (NB * 8)           // 8192
#define N_BANK 1000000LL

__device__ uint32_t g_ticket;
__device__ float    g_acc[2 * NB];

// int64 vs int32 detection: first 16B as two int64 must both be in [0,1e6).
__device__ __forceinline__ bool idx_is64(const void* p)
{
    const longlong2 v = *reinterpret_cast<const longlong2*>(p);
    return (v.x >= 0 && v.x < N_BANK) & (v.y >= 0 && v.y < N_BANK);
}

__global__ void k_init()
{
    const int i = blockIdx.x * blockDim.x + threadIdx.x;
    if (i < 2 * NB) g_acc[i] = 0.0f;
    if (i == 0) g_ticket = 0u;
}

__global__ __launch_bounds__(128, 4)
void la_main(const float* __restrict__ codes,
             const float* __restrict__ bank,
             const void*  __restrict__ idx_bg,
             const void*  __restrict__ idx_cl)
{
    const int lane = threadIdx.x & 31;
    const bool is64 = idx_is64(idx_bg);
    const char* gb = reinterpret_cast<const char*>(bank)
                   + (uint32_t)(lane * 16);

    for (;;) {
        // ---- grab a unit ----
        uint32_t t = 0;
        if (lane == 0) t = atomicAdd(&g_ticket, 1u);
        t = __shfl_sync(0xffffffffu, t, 0);
        if (t >= UNITS) break;
        const int b = (int)(t >> 3);
        const int q = (int)(t & 7u);

        // ---- v_b in registers (lane holds 4 components) ----
        const float4 cv = *reinterpret_cast<const float4*>(
            codes + b * DIM + lane * 4);
        float ss = cv.x * cv.x + cv.y * cv.y + cv.z * cv.z + cv.w * cv.w;
        #pragma unroll
        for (int o = 16; o; o >>= 1)
            ss += __shfl_xor_sync(0xffffffffu, ss, o);
        const float inv = rsqrtf(ss);
        const float4 vv = make_float4(cv.x * inv, cv.y * inv,
                                      cv.z * inv, cv.w * inv);

        // ---- this unit's 25+25 indices -> u32 byte offsets in lane regs ----
        const long long base = (long long)b * KNEI + q * PPU;
        uint32_t myo1 = 0, myo2 = 0;
        if (lane < PPU) {
            if (is64) {
                myo1 = (uint32_t)((const long long*)idx_bg)[base + lane] * 512u;
                myo2 = (uint32_t)((const long long*)idx_cl)[base + lane] * 512u;
            } else {
                myo1 = (uint32_t)((const int*)idx_bg)[base + lane] * 512u;
                myo2 = (uint32_t)((const int*)idx_cl)[base + lane] * 512u;
            }
        }

        float s1 = 0.0f, s2 = 0.0f;

        #pragma unroll
        for (int tb = 0; tb < PPU / 5; ++tb) {
            float4 a[5], g[5];
            // 10 independent 512B gathers in flight
            #pragma unroll
            for (int u = 0; u < 5; ++u) {
                const uint32_t o1 =
                    __shfl_sync(0xffffffffu, myo1, tb * 5 + u);
                const uint32_t o2 =
                    __shfl_sync(0xffffffffu, myo2, tb * 5 + u);
                a[u] = __ldg(reinterpret_cast<const float4*>(gb + o1));
                g[u] = __ldg(reinterpret_cast<const float4*>(gb + o2));
            }
            #pragma unroll
            for (int u = 0; u < 5; ++u) {
                float d1 = a[u].x * vv.x + a[u].y * vv.y
                         + a[u].z * vv.z + a[u].w * vv.w;
                float d2 = g[u].x * vv.x + g[u].y * vv.y
                         + g[u].z * vv.z + g[u].w * vv.w;
                #pragma unroll
                for (int o = 16; o; o >>= 1) {
                    d1 += __shfl_xor_sync(0xffffffffu, d1, o);
                    d2 += __shfl_xor_sync(0xffffffffu, d2, o);
                }
                s1 += __expf(d1 * TINV);
                s2 += __expf(d2 * TINV);
            }
        }

        if (lane == 0) {
            atomicAdd(&g_acc[2 * b],     s1);
            atomicAdd(&g_acc[2 * b + 1], s2);
        }
    }
}

__global__ void k_final(float* __restrict__ out)
{
    const int b = blockIdx.x * blockDim.x + threadIdx.x;
    if (b < NB)
        out[b] = __logf(g_acc[2 * b]) - __logf(g_acc[2 * b + 1]);
}

extern "C" void kernel_launch(void* const* d_in, const int* in_sizes, int n_in,
                              void* d_out, int out_size)
{
    const float* codes  = (const float*)d_in[0];
    const float* bank   = (const float*)d_in[1];
    const void*  idx_bg = d_in[2];
    const void*  idx_cl = d_in[3];
    float*       out    = (float*)d_out;

    k_init<<<8, 256>>>();
    la_main<<<592, 128>>>(codes, bank, idx_bg, idx_cl);   // 4 CTAs/SM x 148
    k_final<<<8, 128>>>(out);
}

// round 12
// speedup vs baseline: 1.0065x; 1.0065x over previous
#include <cuda_runtime.h>
#include <cstdint>

// LocalAggregationLoss — single-launch work-stealing kernel, self-cleaning
// state (graph-replay safe, no init/final launches).
//   Units: (b, eighth) = 25 row-pairs; 8192 units via atomic ticket.
//   Finalization by completion count: 8th finisher of b writes out[b] and
//   resets b's accumulators; last ticket grab resets the ticket.

#define DIM    128
#define KNEI   200
#define NB     1024
#define TINV   (1.0f / 0.07f)
#define PPU    25                 // pairs per unit
#define UNITS  (NB * 8)           // 8192
#define GRID   592                // 4 CTAs/SM x 148
#define NWARP  4
#define WTOT   (GRID * NWARP)     // total warps = failing grabs
#define N_BANK 1000000LL

__device__ uint32_t g_ticket;        // zero at load; self-resets each launch
__device__ uint32_t g_done[NB];      // zero at load; self-resets
__device__ float    g_acc[2 * NB];   // zero at load; self-resets

// int64 vs int32 detection: first 16B as two int64 must both be in [0,1e6).
__device__ __forceinline__ bool idx_is64(const void* p)
{
    const longlong2 v = *reinterpret_cast<const longlong2*>(p);
    return (v.x >= 0 && v.x < N_BANK) & (v.y >= 0 && v.y < N_BANK);
}

__global__ __launch_bounds__(NWARP * 32, 4)
void la_main(const float* __restrict__ codes,
             const float* __restrict__ bank,
             const void*  __restrict__ idx_bg,
             const void*  __restrict__ idx_cl,
             float* __restrict__ out)
{
    const int lane = threadIdx.x & 31;
    const bool is64 = idx_is64(idx_bg);
    const char* gb = reinterpret_cast<const char*>(bank)
                   + (uint32_t)(lane * 16);

    for (;;) {
        // ---- grab a unit ----
        uint32_t t = 0;
        if (lane == 0) t = atomicAdd(&g_ticket, 1u);
        t = __shfl_sync(0xffffffffu, t, 0);
        if (t >= UNITS) {
            // exactly WTOT failing grabs happen; the holder of the last
            // ticket value resets the counter for the next graph replay.
            if (lane == 0 && t == UNITS + WTOT - 1) g_ticket = 0u;
            break;
        }
        const int b = (int)(t >> 3);
        const int q = (int)(t & 7u);

        // ---- v_b in registers (lane holds 4 components) ----
        const float4 cv = *reinterpret_cast<const float4*>(
            codes + b * DIM + lane * 4);
        float ss = cv.x * cv.x + cv.y * cv.y + cv.z * cv.z + cv.w * cv.w;
        #pragma unroll
        for (int o = 16; o; o >>= 1)
            ss += __shfl_xor_sync(0xffffffffu, ss, o);
        const float inv = rsqrtf(ss);
        const float4 vv = make_float4(cv.x * inv, cv.y * inv,
                                      cv.z * inv, cv.w * inv);

        // ---- unit's 25+25 indices -> u32 byte offsets in lane regs ----
        const long long base = (long long)b * KNEI + q * PPU;
        uint32_t myo1 = 0, myo2 = 0;
        if (lane < PPU) {
            if (is64) {
                myo1 = (uint32_t)((const long long*)idx_bg)[base + lane] * 512u;
                myo2 = (uint32_t)((const long long*)idx_cl)[base + lane] * 512u;
            } else {
                myo1 = (uint32_t)((const int*)idx_bg)[base + lane] * 512u;
                myo2 = (uint32_t)((const int*)idx_cl)[base + lane] * 512u;
            }
        }

        float s1 = 0.0f, s2 = 0.0f;

        #pragma unroll
        for (int tb = 0; tb < PPU / 5; ++tb) {
            float4 a[5], g[5];
            // 10 independent 512B gathers in flight
            #pragma unroll
            for (int u = 0; u < 5; ++u) {
                const uint32_t o1 = __shfl_sync(0xffffffffu, myo1, tb * 5 + u);
                const uint32_t o2 = __shfl_sync(0xffffffffu, myo2, tb * 5 + u);
                a[u] = __ldg(reinterpret_cast<const float4*>(gb + o1));
                g[u] = __ldg(reinterpret_cast<const float4*>(gb + o2));
            }
            #pragma unroll
            for (int u = 0; u < 5; ++u) {
                float d1 = a[u].x * vv.x + a[u].y * vv.y
                         + a[u].z * vv.z + a[u].w * vv.w;
                float d2 = g[u].x * vv.x + g[u].y * vv.y
                         + g[u].z * vv.z + g[u].w * vv.w;
                #pragma unroll
                for (int o = 16; o; o >>= 1) {
                    d1 += __shfl_xor_sync(0xffffffffu, d1, o);
                    d2 += __shfl_xor_sync(0xffffffffu, d2, o);
                }
                s1 += __expf(d1 * TINV);
                s2 += __expf(d2 * TINV);
            }
        }

        if (lane == 0) {
            atomicAdd(&g_acc[2 * b],     s1);
            atomicAdd(&g_acc[2 * b + 1], s2);
            __threadfence();                       // publish before counting
            const uint32_t d = atomicAdd(&g_done[b], 1u);
            if (d == 7u) {                         // last unit of this b
                __threadfence();
                // L2-coherent reads of the final sums
                const float S1 = atomicAdd(&g_acc[2 * b],     0.0f);
                const float S2 = atomicAdd(&g_acc[2 * b + 1], 0.0f);
                out[b] = __logf(S1) - __logf(S2);
                // self-clean for the next graph replay
                g_acc[2 * b]     = 0.0f;
                g_acc[2 * b + 1] = 0.0f;
                g_done[b]        = 0u;
            }
        }
    }
}

extern "C" void kernel_launch(void* const* d_in, const int* in_sizes, int n_in,
                              void* d_out, int out_size)
{
    const float* codes  = (const float*)d_in[0];
    const float* bank   = (const float*)d_in[1];
    const void*  idx_bg = d_in[2];
    const void*  idx_cl = d_in[3];
    float*       out    = (float*)d_out;

    la_main<<<GRID, NWARP * 32>>>(codes, bank, idx_bg, idx_cl, out);
}